// round 9
// baseline (speedup 1.0000x reference)
#include <cuda_runtime.h>
#include <cuda_bf16.h>

// ---------------------------------------------------------------------------
// GATv2 GraphEncoder: N=50000 nodes, E=800000 edges (+N self loops), 4 layers.
// Layer 0 collapses exactly to a 3-type table lookup (x has 3 distinct rows).
// Layers 1-3: split-bf16 tensor-core GEMMs + 4-edge-group online softmax agg.
// ---------------------------------------------------------------------------

#define MAXN  50000
#define MAXNP 50176          // padded to multiple of 64 rows for mma tiles
#define MAXE  800000

__device__ float g_x  [MAXN  * 128];  // current node features (residual)
__device__ float g_xl [MAXNP * 128];  // x @ Wl
__device__ float g_xr [MAXNP * 128];  // x @ Wr
__device__ __nv_bfloat16 g_xh [MAXNP * 128];  // bf16 hi of x
__device__ __nv_bfloat16 g_xlo[MAXNP * 128];  // bf16 lo of x
__device__ unsigned int g_wf[3][4][8192];     // frag-swizzled W: {Lhi,Llo,Rhi,Rlo}
__device__ float g_tab[3 * 128];              // layer-0 XLtab (3 types x 128)
__device__ float g_l0[9 * 4];                 // layer-0 logits [td][ts][h]
__device__ int   g_cnt[MAXN];
__device__ int   g_off[MAXN + 1];
__device__ int   g_cur[MAXN + 1];
__device__ int   g_csr[MAXE + MAXN];
__device__ int   g_sums[128];

// ------------------------------ CSR build ---------------------------------

__global__ void k_hist(const int* __restrict__ dst, int e) {
    int i = blockIdx.x * blockDim.x + threadIdx.x;
    if (i < e) atomicAdd(&g_cnt[dst[i]], 1);
}

// inclusive scan within 1024-blocks (shfl-based); +1 folds the self loop in
__global__ void k_scan_blocks(int n) {
    __shared__ int wsum[32];
    int t = threadIdx.x;
    int i = blockIdx.x * 1024 + t;
    int lane = t & 31, w = t >> 5;
    int v = (i < n) ? g_cnt[i] + 1 : 0;
    #pragma unroll
    for (int o = 1; o < 32; o <<= 1) {
        int u = __shfl_up_sync(0xffffffffu, v, o);
        if (lane >= o) v += u;
    }
    if (lane == 31) wsum[w] = v;
    __syncthreads();
    if (w == 0) {
        int s = wsum[lane];
        #pragma unroll
        for (int o = 1; o < 32; o <<= 1) {
            int u = __shfl_up_sync(0xffffffffu, s, o);
            if (lane >= o) s += u;
        }
        wsum[lane] = s;
    }
    __syncthreads();
    if (w > 0) v += wsum[w - 1];
    if (i < n) g_off[i + 1] = v;
    if (t == 1023) g_sums[blockIdx.x] = v;
}

__global__ void k_scan_finish(int n) {
    __shared__ int pre;
    int blk = (blockIdx.x * 256) >> 10;
    if (threadIdx.x == 0) {
        int r = 0;
        #pragma unroll 8
        for (int b = 0; b < blk; b++) r += g_sums[b];
        pre = r;
    }
    __syncthreads();
    int i = blockIdx.x * 256 + threadIdx.x;
    if (i < n) {
        int v = g_off[i + 1] + pre;
        g_off[i + 1] = v;
        g_cur[i + 1] = v;
    }
    if (i == 0) { g_off[0] = 0; g_cur[0] = 0; }
}

__global__ void k_scatter(const int* __restrict__ src, const int* __restrict__ dst,
                          int e, int n) {
    int i = blockIdx.x * blockDim.x + threadIdx.x;
    if (i >= e + n) return;
    int s, d;
    if (i < e) { s = src[i]; d = dst[i]; }
    else       { s = i - e;  d = s; }
    int pos = atomicAdd(&g_cur[d], 1);
    g_csr[pos] = s;
}

// ------------------------- layer-0 table precompute -------------------------
// x has only 3 distinct rows (emb per node type): precompute XLtab/XRtab and
// the 9x4 logit table; layer 0 then reduces to counting neighbor types.

__device__ __forceinline__ float lrelu(float x) { return x > 0.0f ? x : 0.2f * x; }

__global__ void k_prep0(const float* __restrict__ emb, const float* __restrict__ Wl,
                        const float* __restrict__ Wr, const float* __restrict__ att) {
    __shared__ float xl[3][128], xr[3][128];
    int ch = threadIdx.x;            // 128 threads
    #pragma unroll
    for (int t = 0; t < 3; t++) {
        float al = 0.f, ar = 0.f;
        #pragma unroll
        for (int k = 0; k < 16; k++) {
            float e = emb[t * 16 + k];
            al += e * Wl[k * 128 + ch];
            ar += e * Wr[k * 128 + ch];
        }
        xl[t][ch] = al;
        xr[t][ch] = ar;
        g_tab[t * 128 + ch] = al;
    }
    __syncthreads();
    if (ch < 36) {                   // (td, ts, h) combos
        int td = ch / 12, ts = (ch / 4) % 3, h = ch % 4;
        float l = 0.f;
        #pragma unroll
        for (int d = 0; d < 32; d++) {
            int c = h * 32 + d;
            l += lrelu(xl[ts][c] + xr[td][c]) * att[c];
        }
        g_l0[(td * 3 + ts) * 4 + h] = l;
    }
}

__device__ __forceinline__ unsigned int pack2bf(float a, float b) {
    __nv_bfloat162 v = __floats2bfloat162_rn(a, b);
    return *reinterpret_cast<unsigned int*>(&v);
}

// layer-0 aggregation: warp/node, count neighbor types, closed-form softmax.
__global__ void __launch_bounds__(256)
k_agg0(const int* __restrict__ nt, const float* __restrict__ bias,
       const float* __restrict__ lng, const float* __restrict__ lnb, int n) {
    int v = (blockIdx.x * blockDim.x + threadIdx.x) >> 5;
    int lane = threadIdx.x & 31;
    if (v >= n) return;
    int td = nt[v];

    int s0 = g_off[v], s1 = g_off[v + 1];
    int c0 = 0, c1 = 0, c2 = 0;
    for (int p = s0 + lane; p < s1; p += 32) {
        int ts = nt[g_csr[p]];
        c0 += (ts == 0); c1 += (ts == 1); c2 += (ts == 2);
    }
    c0 = __reduce_add_sync(0xffffffffu, c0);
    c1 = __reduce_add_sync(0xffffffffu, c1);
    c2 = __reduce_add_sync(0xffffffffu, c2);

    int h = lane >> 3;               // head of this lane's 4 channels
    float l0 = g_l0[(td * 3 + 0) * 4 + h];
    float l1 = g_l0[(td * 3 + 1) * 4 + h];
    float l2 = g_l0[(td * 3 + 2) * 4 + h];
    float mx = fmaxf(l0, fmaxf(l1, l2));
    float w0 = (float)c0 * __expf(l0 - mx);
    float w1 = (float)c1 * __expf(l1 - mx);
    float w2 = (float)c2 * __expf(l2 - mx);
    float inv = 1.0f / (w0 + w1 + w2);
    w0 *= inv; w1 *= inv; w2 *= inv;

    float4 t0 = *(const float4*)(g_tab + 0 * 128 + lane * 4);
    float4 t1 = *(const float4*)(g_tab + 1 * 128 + lane * 4);
    float4 t2 = *(const float4*)(g_tab + 2 * 128 + lane * 4);
    float4 bv = __ldg((const float4*)(bias + lane * 4));
    float v0 = w0 * t0.x + w1 * t1.x + w2 * t2.x + bv.x;
    float v1 = w0 * t0.y + w1 * t1.y + w2 * t2.y + bv.y;
    float v2 = w0 * t0.z + w1 * t1.z + w2 * t2.z + bv.z;
    float v3 = w0 * t0.w + w1 * t1.w + w2 * t2.w + bv.w;

    // layernorm + relu
    float sum = v0 + v1 + v2 + v3;
    #pragma unroll
    for (int o = 16; o > 0; o >>= 1) sum += __shfl_xor_sync(0xffffffffu, sum, o);
    float mean = sum * (1.0f / 128.0f);
    float d0 = v0 - mean, d1 = v1 - mean, d2 = v2 - mean, d3 = v3 - mean;
    float sq = d0 * d0 + d1 * d1 + d2 * d2 + d3 * d3;
    #pragma unroll
    for (int o = 16; o > 0; o >>= 1) sq += __shfl_xor_sync(0xffffffffu, sq, o);
    float rstd = rsqrtf(sq * (1.0f / 128.0f) + 1e-5f);

    float4 gv = __ldg((const float4*)(lng + lane * 4));
    float4 lb4 = __ldg((const float4*)(lnb + lane * 4));
    float4 o4;
    o4.x = fmaxf(d0 * rstd * gv.x + lb4.x, 0.0f);
    o4.y = fmaxf(d1 * rstd * gv.y + lb4.y, 0.0f);
    o4.z = fmaxf(d2 * rstd * gv.z + lb4.z, 0.0f);
    o4.w = fmaxf(d3 * rstd * gv.w + lb4.w, 0.0f);

    int base = v * 128 + lane * 4;
    *(float4*)(g_x + base) = o4;
    float h0 = __bfloat162float(__float2bfloat16(o4.x));
    float h1 = __bfloat162float(__float2bfloat16(o4.y));
    float h2 = __bfloat162float(__float2bfloat16(o4.z));
    float h3 = __bfloat162float(__float2bfloat16(o4.w));
    unsigned int* XH  = (unsigned int*)g_xh;
    unsigned int* XLO = (unsigned int*)g_xlo;
    *(uint2*)&XH[v * 64 + lane * 2] =
        make_uint2(pack2bf(o4.x, o4.y), pack2bf(o4.z, o4.w));
    *(uint2*)&XLO[v * 64 + lane * 2] =
        make_uint2(pack2bf(o4.x - h0, o4.y - h1), pack2bf(o4.z - h2, o4.w - h3));
}

// ------------------------- weight frag preparation --------------------------

__global__ void k_prepW(const float* __restrict__ W0, const float* __restrict__ W1,
                        const float* __restrict__ W2, const float* __restrict__ W3,
                        const float* __restrict__ W4, const float* __restrict__ W5) {
    int tid = blockIdx.x * 256 + threadIdx.x;
    if (tid >= 6 * 8 * 16 * 32) return;
    int lane = tid & 31;
    int r = tid >> 5;
    int n8 = r & 15; r >>= 4;
    int ks = r & 7;  r >>= 3;
    int m = r;
    const float* W;
    switch (m) { case 0: W = W0; break; case 1: W = W1; break;
                 case 2: W = W2; break; case 3: W = W3; break;
                 case 4: W = W4; break; default: W = W5; }
    int g = lane >> 2, t = lane & 3;
    int k0 = ks * 16, n0 = n8 * 8;
    float w00 = W[(k0 + 2 * t)     * 128 + n0 + g];
    float w01 = W[(k0 + 2 * t + 1) * 128 + n0 + g];
    float w10 = W[(k0 + 2 * t + 8) * 128 + n0 + g];
    float w11 = W[(k0 + 2 * t + 9) * 128 + n0 + g];
    float h00 = __bfloat162float(__float2bfloat16(w00));
    float h01 = __bfloat162float(__float2bfloat16(w01));
    float h10 = __bfloat162float(__float2bfloat16(w10));
    float h11 = __bfloat162float(__float2bfloat16(w11));
    int li = m >> 1, mat = m & 1;
    unsigned int* oh = g_wf[li][mat * 2 + 0];
    unsigned int* ol = g_wf[li][mat * 2 + 1];
    int idx = ((ks * 16 + n8) * 32 + lane) * 2;
    oh[idx]     = pack2bf(w00, w01);
    oh[idx + 1] = pack2bf(w10, w11);
    ol[idx]     = pack2bf(w00 - h00, w01 - h01);
    ol[idx + 1] = pack2bf(w10 - h10, w11 - h11);
}

// ------------------------------ tensor GEMMs -------------------------------

#define MMA_BF16(D, A0, A1, A2, A3, B0, B1)                                   \
    asm volatile("mma.sync.aligned.m16n8k16.row.col.f32.bf16.bf16.f32 "       \
                 "{%0,%1,%2,%3}, {%4,%5,%6,%7}, {%8,%9}, {%0,%1,%2,%3};"      \
                 : "+f"(D[0]), "+f"(D[1]), "+f"(D[2]), "+f"(D[3])             \
                 : "r"(A0), "r"(A1), "r"(A2), "r"(A3), "r"(B0), "r"(B1))

__global__ void __launch_bounds__(256) k_gemm_t(int li) {
    int lane = threadIdx.x & 31, warp = threadIdx.x >> 5;
    int g = lane >> 2, t = lane & 3;
    int wr = warp >> 1, wc = warp & 1;
    int r0 = blockIdx.x * 64 + wr * 16;

    const unsigned int* XH  = (const unsigned int*)g_xh;
    const unsigned int* XLO = (const unsigned int*)g_xlo;
    const unsigned int* lh = g_wf[li][0];
    const unsigned int* ll = g_wf[li][1];
    const unsigned int* rh = g_wf[li][2];
    const unsigned int* rl = g_wf[li][3];

    float dl[8][4], dr[8][4];
    #pragma unroll
    for (int i = 0; i < 8; i++)
        #pragma unroll
        for (int j = 0; j < 4; j++) { dl[i][j] = 0.0f; dr[i][j] = 0.0f; }

    int rowA = (r0 + g) * 64;
    int rowB = (r0 + g + 8) * 64;

    #pragma unroll
    for (int ks = 0; ks < 8; ks++) {
        int kb = ks * 8 + t;
        unsigned int ah0 = __ldg(XH + rowA + kb),     ah1 = __ldg(XH + rowB + kb);
        unsigned int ah2 = __ldg(XH + rowA + kb + 4), ah3 = __ldg(XH + rowB + kb + 4);
        unsigned int al0 = __ldg(XLO + rowA + kb),     al1 = __ldg(XLO + rowB + kb);
        unsigned int al2 = __ldg(XLO + rowA + kb + 4), al3 = __ldg(XLO + rowB + kb + 4);
        #pragma unroll
        for (int n8 = 0; n8 < 8; n8++) {
            int nn = wc * 8 + n8;
            int bidx = ((ks * 16 + nn) * 32 + lane) * 2;
            uint2 bh = __ldg((const uint2*)(lh + bidx));
            uint2 bl = __ldg((const uint2*)(ll + bidx));
            MMA_BF16(dl[n8], ah0, ah1, ah2, ah3, bh.x, bh.y);
            MMA_BF16(dl[n8], ah0, ah1, ah2, ah3, bl.x, bl.y);
            MMA_BF16(dl[n8], al0, al1, al2, al3, bh.x, bh.y);
            uint2 ch = __ldg((const uint2*)(rh + bidx));
            uint2 cl = __ldg((const uint2*)(rl + bidx));
            MMA_BF16(dr[n8], ah0, ah1, ah2, ah3, ch.x, ch.y);
            MMA_BF16(dr[n8], ah0, ah1, ah2, ah3, cl.x, cl.y);
            MMA_BF16(dr[n8], al0, al1, al2, al3, ch.x, ch.y);
        }
    }

    #pragma unroll
    for (int n8 = 0; n8 < 8; n8++) {
        int c = (wc * 8 + n8) * 8 + 2 * t;
        *(float2*)&g_xl[(r0 + g)     * 128 + c] = make_float2(dl[n8][0], dl[n8][1]);
        *(float2*)&g_xl[(r0 + g + 8) * 128 + c] = make_float2(dl[n8][2], dl[n8][3]);
        *(float2*)&g_xr[(r0 + g)     * 128 + c] = make_float2(dr[n8][0], dr[n8][1]);
        *(float2*)&g_xr[(r0 + g + 8) * 128 + c] = make_float2(dr[n8][2], dr[n8][3]);
    }
}

// --------------------------- edge aggregation ------------------------------
// 1 warp/node; 4 edges per iteration (4 independent shfl chains, one rescale
// per group); rows prefetched 1 group ahead, CSR indices 2 groups ahead.

template<int SEGW, int IS_FINAL>
__global__ void __launch_bounds__(256)
k_agg4(const float* __restrict__ att, const float* __restrict__ bias,
       const float* __restrict__ lng, const float* __restrict__ lnb,
       int n, float* __restrict__ dout) {
    int v = (blockIdx.x * blockDim.x + threadIdx.x) >> 5;
    int lane = threadIdx.x & 31;
    if (v >= n) return;
    int base = v * 128 + lane * 4;

    float4 xrv = *(const float4*)(g_xr + base);
    float4 av  = __ldg((const float4*)(att + lane * 4));

    float m = -1e30f, z = 0.0f;
    float a0 = 0.f, a1 = 0.f, a2 = 0.f, a3 = 0.f;

    const float4* __restrict__ XL = (const float4*)g_xl;
    const int* __restrict__ CSR = g_csr;
    int s0 = g_off[v], s1 = g_off[v + 1];
    int last = s1 - 1;
    #define LDI(q) CSR[(q) < s1 ? (q) : last]

    int ia[4], ib[4];
    float4 X[4];
    #pragma unroll
    for (int j = 0; j < 4; j++) ia[j] = LDI(s0 + j);
    #pragma unroll
    for (int j = 0; j < 4; j++) X[j] = __ldg(XL + ia[j] * 32 + lane);
    #pragma unroll
    for (int j = 0; j < 4; j++) ib[j] = LDI(s0 + 4 + j);

    int p = s0;
    while (p < s1) {
        float4 A[4];
        #pragma unroll
        for (int j = 0; j < 4; j++) A[j] = X[j];
        int rem = s1 - p;
        // prefetch rows for next group, indices for group after
        #pragma unroll
        for (int j = 0; j < 4; j++) X[j] = __ldg(XL + ib[j] * 32 + lane);
        #pragma unroll
        for (int j = 0; j < 4; j++) ia[j] = LDI(p + 8 + j);

        float l[4];
        #pragma unroll
        for (int j = 0; j < 4; j++)
            l[j] = lrelu(A[j].x + xrv.x) * av.x + lrelu(A[j].y + xrv.y) * av.y
                 + lrelu(A[j].z + xrv.z) * av.z + lrelu(A[j].w + xrv.w) * av.w;
        #pragma unroll
        for (int o = SEGW >> 1; o > 0; o >>= 1) {
            #pragma unroll
            for (int j = 0; j < 4; j++)
                l[j] += __shfl_xor_sync(0xffffffffu, l[j], o, SEGW);
        }
        if (rem < 4) {
            if (rem < 2) l[1] = -1e30f;
            if (rem < 3) l[2] = -1e30f;
            l[3] = (rem < 4) ? -1e30f : l[3];
        }

        float mn = fmaxf(fmaxf(m, fmaxf(l[0], l[1])), fmaxf(l[2], l[3]));
        float sc = __expf(m - mn);
        float p0 = __expf(l[0] - mn);
        float p1 = __expf(l[1] - mn);
        float p2 = __expf(l[2] - mn);
        float p3 = __expf(l[3] - mn);
        z  = z  * sc + p0 + p1 + p2 + p3;
        a0 = a0 * sc + p0 * A[0].x + p1 * A[1].x + p2 * A[2].x + p3 * A[3].x;
        a1 = a1 * sc + p0 * A[0].y + p1 * A[1].y + p2 * A[2].y + p3 * A[3].y;
        a2 = a2 * sc + p0 * A[0].z + p1 * A[1].z + p2 * A[2].z + p3 * A[3].z;
        a3 = a3 * sc + p0 * A[0].w + p1 * A[1].w + p2 * A[2].w + p3 * A[3].w;
        m = mn;
        p += 4;
        #pragma unroll
        for (int j = 0; j < 4; j++) ib[j] = ia[j];
    }
    #undef LDI

    float inv = 1.0f / z;
    float4 bv = __ldg((const float4*)(bias + lane * 4));
    float v0 = a0 * inv + bv.x;
    float v1 = a1 * inv + bv.y;
    float v2 = a2 * inv + bv.z;
    float v3 = a3 * inv + bv.w;
    {   // residual (always present for layers 1-3)
        float4 rv = *(const float4*)(g_x + base);
        v0 += rv.x; v1 += rv.y; v2 += rv.z; v3 += rv.w;
    }

    float sum = v0 + v1 + v2 + v3;
    #pragma unroll
    for (int o = 16; o > 0; o >>= 1) sum += __shfl_xor_sync(0xffffffffu, sum, o);
    float mean = sum * (1.0f / 128.0f);
    float d0 = v0 - mean, d1 = v1 - mean, d2 = v2 - mean, d3 = v3 - mean;
    float sq = d0 * d0 + d1 * d1 + d2 * d2 + d3 * d3;
    #pragma unroll
    for (int o = 16; o > 0; o >>= 1) sq += __shfl_xor_sync(0xffffffffu, sq, o);
    float rstd = rsqrtf(sq * (1.0f / 128.0f) + 1e-5f);

    float4 gv = __ldg((const float4*)(lng + lane * 4));
    float4 lb4 = __ldg((const float4*)(lnb + lane * 4));
    float4 o4;
    o4.x = fmaxf(d0 * rstd * gv.x + lb4.x, 0.0f);
    o4.y = fmaxf(d1 * rstd * gv.y + lb4.y, 0.0f);
    o4.z = fmaxf(d2 * rstd * gv.z + lb4.z, 0.0f);
    o4.w = fmaxf(d3 * rstd * gv.w + lb4.w, 0.0f);

    if (IS_FINAL) {
        *(float4*)(dout + base) = o4;
    } else {
        *(float4*)(g_x + base) = o4;
        float h0 = __bfloat162float(__float2bfloat16(o4.x));
        float h1 = __bfloat162float(__float2bfloat16(o4.y));
        float h2 = __bfloat162float(__float2bfloat16(o4.z));
        float h3 = __bfloat162float(__float2bfloat16(o4.w));
        unsigned int* XH  = (unsigned int*)g_xh;
        unsigned int* XLO = (unsigned int*)g_xlo;
        *(uint2*)&XH[v * 64 + lane * 2] =
            make_uint2(pack2bf(o4.x, o4.y), pack2bf(o4.z, o4.w));
        *(uint2*)&XLO[v * 64 + lane * 2] =
            make_uint2(pack2bf(o4.x - h0, o4.y - h1), pack2bf(o4.z - h2, o4.w - h3));
    }
}

// ------------------------------ launch -------------------------------------

extern "C" void kernel_launch(void* const* d_in, const int* in_sizes, int n_in,
                              void* d_out, int out_size) {
    const int*   node_types = (const int*)d_in[0];
    const int*   edge_index = (const int*)d_in[1];
    const float* emb        = (const float*)d_in[2];
    const float* Wl[4], *Wr[4], *att[4], *bias[4];
    for (int li = 0; li < 4; li++) {
        Wl[li]   = (const float*)d_in[3 + li * 4 + 0];
        Wr[li]   = (const float*)d_in[3 + li * 4 + 1];
        att[li]  = (const float*)d_in[3 + li * 4 + 2];
        bias[li] = (const float*)d_in[3 + li * 4 + 3];
    }
    const float* lng = (const float*)d_in[19];
    const float* lnb = (const float*)d_in[20];
    float* out = (float*)d_out;

    int n = in_sizes[0];
    int e = in_sizes[1] / 2;
    const int* esrc = edge_index;
    const int* edst = edge_index + e;

    // CSR by destination (self loops folded into the scan's +1)
    void* cntp = nullptr;
    cudaGetSymbolAddress(&cntp, g_cnt);
    cudaMemsetAsync(cntp, 0, n * sizeof(int));
    k_hist<<<(e + 255) / 256, 256>>>(edst, e);
    int nb = (n + 1023) / 1024;
    k_scan_blocks<<<nb, 1024>>>(n);
    k_scan_finish<<<(n + 255) / 256, 256>>>(n);
    k_scatter<<<(e + n + 255) / 256, 256>>>(esrc, edst, e, n);

    int ab = (n + 7) / 8;
    int tb = (n + 63) / 64;

    // layer 0 (exact 3-type closed form)
    k_prep0<<<1, 128>>>(emb, Wl[0], Wr[0], att[0]);
    k_agg0<<<ab, 256>>>(node_types, bias[0], lng + 0 * 128, lnb + 0 * 128, n);

    k_prepW<<<96, 256>>>(Wl[1], Wr[1], Wl[2], Wr[2], Wl[3], Wr[3]);

    // layer 1
    k_gemm_t<<<tb, 256>>>(0);
    k_agg4<8, 0><<<ab, 256>>>(att[1], bias[1], lng + 1 * 128, lnb + 1 * 128,
                              n, out);
    // layer 2
    k_gemm_t<<<tb, 256>>>(1);
    k_agg4<8, 0><<<ab, 256>>>(att[2], bias[2], lng + 2 * 128, lnb + 2 * 128,
                              n, out);
    // layer 3
    k_gemm_t<<<tb, 256>>>(2);
    k_agg4<32, 1><<<ab, 256>>>(att[3], bias[3], lng + 3 * 128, lnb + 3 * 128,
                               n, out);
}

// round 10
// speedup vs baseline: 1.6077x; 1.6077x over previous
#include <cuda_runtime.h>
#include <cuda_bf16.h>

// ---------------------------------------------------------------------------
// GATv2 GraphEncoder: N=50000 nodes, E=800000 edges (+N self loops), 4 layers.
// Layer 0 collapses exactly to a 3-type table lookup (x has 3 distinct rows).
// Layers 1-3: split-bf16 tensor-core GEMMs + 2-edge online-softmax agg (R8).
// ---------------------------------------------------------------------------

#define MAXN  50000
#define MAXNP 50176          // padded to multiple of 64 rows for mma tiles
#define MAXE  800000

__device__ float g_x  [MAXN  * 128];  // current node features (residual)
__device__ float g_xl [MAXNP * 128];  // x @ Wl
__device__ float g_xr [MAXNP * 128];  // x @ Wr
__device__ __nv_bfloat16 g_xh [MAXNP * 128];  // bf16 hi of x
__device__ __nv_bfloat16 g_xlo[MAXNP * 128];  // bf16 lo of x
__device__ unsigned int g_wf[3][4][8192];     // frag-swizzled W: {Lhi,Llo,Rhi,Rlo}
__device__ float g_tab[3 * 128];              // layer-0 XLtab (3 types x 128)
__device__ float g_l0[9 * 4];                 // layer-0 logits [td][ts][h]
__device__ int   g_cnt[MAXN];
__device__ int   g_off[MAXN + 1];
__device__ int   g_cur[MAXN + 1];
__device__ int   g_csr[MAXE + MAXN];
__device__ int   g_sums[128];

// ------------------------------ CSR build ---------------------------------

__global__ void k_hist(const int* __restrict__ dst, int e) {
    int i = blockIdx.x * blockDim.x + threadIdx.x;
    if (i < e) atomicAdd(&g_cnt[dst[i]], 1);
}

// inclusive scan within 1024-blocks (shfl-based); +1 folds the self loop in
__global__ void k_scan_blocks(int n) {
    __shared__ int wsum[32];
    int t = threadIdx.x;
    int i = blockIdx.x * 1024 + t;
    int lane = t & 31, w = t >> 5;
    int v = (i < n) ? g_cnt[i] + 1 : 0;
    #pragma unroll
    for (int o = 1; o < 32; o <<= 1) {
        int u = __shfl_up_sync(0xffffffffu, v, o);
        if (lane >= o) v += u;
    }
    if (lane == 31) wsum[w] = v;
    __syncthreads();
    if (w == 0) {
        int s = wsum[lane];
        #pragma unroll
        for (int o = 1; o < 32; o <<= 1) {
            int u = __shfl_up_sync(0xffffffffu, s, o);
            if (lane >= o) s += u;
        }
        wsum[lane] = s;
    }
    __syncthreads();
    if (w > 0) v += wsum[w - 1];
    if (i < n) g_off[i + 1] = v;
    if (t == 1023) g_sums[blockIdx.x] = v;
}

__global__ void k_scan_finish(int n) {
    __shared__ int pre;
    int blk = (blockIdx.x * 256) >> 10;
    if (threadIdx.x == 0) {
        int r = 0;
        #pragma unroll 8
        for (int b = 0; b < blk; b++) r += g_sums[b];
        pre = r;
    }
    __syncthreads();
    int i = blockIdx.x * 256 + threadIdx.x;
    if (i < n) {
        int v = g_off[i + 1] + pre;
        g_off[i + 1] = v;
        g_cur[i + 1] = v;
    }
    if (i == 0) { g_off[0] = 0; g_cur[0] = 0; }
}

__global__ void k_scatter(const int* __restrict__ src, const int* __restrict__ dst,
                          int e, int n) {
    int i = blockIdx.x * blockDim.x + threadIdx.x;
    if (i >= e + n) return;
    int s, d;
    if (i < e) { s = src[i]; d = dst[i]; }
    else       { s = i - e;  d = s; }
    int pos = atomicAdd(&g_cur[d], 1);
    g_csr[pos] = s;
}

// ------------------------- layer-0 table precompute -------------------------
// x has only 3 distinct rows (emb per node type): precompute XLtab and the
// 9x4 logit table; layer 0 then reduces to counting neighbor types. Exact.

__device__ __forceinline__ float lrelu(float x) { return x > 0.0f ? x : 0.2f * x; }

__global__ void k_prep0(const float* __restrict__ emb, const float* __restrict__ Wl,
                        const float* __restrict__ Wr, const float* __restrict__ att) {
    __shared__ float xl[3][128], xr[3][128];
    int ch = threadIdx.x;            // 128 threads
    #pragma unroll
    for (int t = 0; t < 3; t++) {
        float al = 0.f, ar = 0.f;
        #pragma unroll
        for (int k = 0; k < 16; k++) {
            float e = emb[t * 16 + k];
            al += e * Wl[k * 128 + ch];
            ar += e * Wr[k * 128 + ch];
        }
        xl[t][ch] = al;
        xr[t][ch] = ar;
        g_tab[t * 128 + ch] = al;
    }
    __syncthreads();
    if (ch < 36) {                   // (td, ts, h) combos
        int td = ch / 12, ts = (ch / 4) % 3, h = ch % 4;
        float l = 0.f;
        #pragma unroll
        for (int d = 0; d < 32; d++) {
            int c = h * 32 + d;
            l += lrelu(xl[ts][c] + xr[td][c]) * att[c];
        }
        g_l0[(td * 3 + ts) * 4 + h] = l;
    }
}

__device__ __forceinline__ unsigned int pack2bf(float a, float b) {
    __nv_bfloat162 v = __floats2bfloat162_rn(a, b);
    return *reinterpret_cast<unsigned int*>(&v);
}

// layer-0 aggregation: warp/node, count neighbor types, closed-form softmax.
__global__ void __launch_bounds__(256)
k_agg0(const int* __restrict__ nt, const float* __restrict__ bias,
       const float* __restrict__ lng, const float* __restrict__ lnb, int n) {
    int v = (blockIdx.x * blockDim.x + threadIdx.x) >> 5;
    int lane = threadIdx.x & 31;
    if (v >= n) return;
    int td = nt[v];

    int s0 = g_off[v], s1 = g_off[v + 1];
    int c0 = 0, c1 = 0, c2 = 0;
    for (int p = s0 + lane; p < s1; p += 32) {
        int ts = nt[g_csr[p]];
        c0 += (ts == 0); c1 += (ts == 1); c2 += (ts == 2);
    }
    c0 = __reduce_add_sync(0xffffffffu, c0);
    c1 = __reduce_add_sync(0xffffffffu, c1);
    c2 = __reduce_add_sync(0xffffffffu, c2);

    int h = lane >> 3;               // head of this lane's 4 channels
    float l0 = g_l0[(td * 3 + 0) * 4 + h];
    float l1 = g_l0[(td * 3 + 1) * 4 + h];
    float l2 = g_l0[(td * 3 + 2) * 4 + h];
    float mx = fmaxf(l0, fmaxf(l1, l2));
    float w0 = (float)c0 * __expf(l0 - mx);
    float w1 = (float)c1 * __expf(l1 - mx);
    float w2 = (float)c2 * __expf(l2 - mx);
    float inv = 1.0f / (w0 + w1 + w2);
    w0 *= inv; w1 *= inv; w2 *= inv;

    float4 t0 = *(const float4*)(g_tab + 0 * 128 + lane * 4);
    float4 t1 = *(const float4*)(g_tab + 1 * 128 + lane * 4);
    float4 t2 = *(const float4*)(g_tab + 2 * 128 + lane * 4);
    float4 bv = __ldg((const float4*)(bias + lane * 4));
    float v0 = w0 * t0.x + w1 * t1.x + w2 * t2.x + bv.x;
    float v1 = w0 * t0.y + w1 * t1.y + w2 * t2.y + bv.y;
    float v2 = w0 * t0.z + w1 * t1.z + w2 * t2.z + bv.z;
    float v3 = w0 * t0.w + w1 * t1.w + w2 * t2.w + bv.w;

    // layernorm + relu
    float sum = v0 + v1 + v2 + v3;
    #pragma unroll
    for (int o = 16; o > 0; o >>= 1) sum += __shfl_xor_sync(0xffffffffu, sum, o);
    float mean = sum * (1.0f / 128.0f);
    float d0 = v0 - mean, d1 = v1 - mean, d2 = v2 - mean, d3 = v3 - mean;
    float sq = d0 * d0 + d1 * d1 + d2 * d2 + d3 * d3;
    #pragma unroll
    for (int o = 16; o > 0; o >>= 1) sq += __shfl_xor_sync(0xffffffffu, sq, o);
    float rstd = rsqrtf(sq * (1.0f / 128.0f) + 1e-5f);

    float4 gv = __ldg((const float4*)(lng + lane * 4));
    float4 lb4 = __ldg((const float4*)(lnb + lane * 4));
    float4 o4;
    o4.x = fmaxf(d0 * rstd * gv.x + lb4.x, 0.0f);
    o4.y = fmaxf(d1 * rstd * gv.y + lb4.y, 0.0f);
    o4.z = fmaxf(d2 * rstd * gv.z + lb4.z, 0.0f);
    o4.w = fmaxf(d3 * rstd * gv.w + lb4.w, 0.0f);

    int base = v * 128 + lane * 4;
    *(float4*)(g_x + base) = o4;
    float h0 = __bfloat162float(__float2bfloat16(o4.x));
    float h1 = __bfloat162float(__float2bfloat16(o4.y));
    float h2 = __bfloat162float(__float2bfloat16(o4.z));
    float h3 = __bfloat162float(__float2bfloat16(o4.w));
    unsigned int* XH  = (unsigned int*)g_xh;
    unsigned int* XLO = (unsigned int*)g_xlo;
    *(uint2*)&XH[v * 64 + lane * 2] =
        make_uint2(pack2bf(o4.x, o4.y), pack2bf(o4.z, o4.w));
    *(uint2*)&XLO[v * 64 + lane * 2] =
        make_uint2(pack2bf(o4.x - h0, o4.y - h1), pack2bf(o4.z - h2, o4.w - h3));
}

// ------------------------- weight frag preparation --------------------------

__global__ void k_prepW(const float* __restrict__ W0, const float* __restrict__ W1,
                        const float* __restrict__ W2, const float* __restrict__ W3,
                        const float* __restrict__ W4, const float* __restrict__ W5) {
    int tid = blockIdx.x * 256 + threadIdx.x;
    if (tid >= 6 * 8 * 16 * 32) return;
    int lane = tid & 31;
    int r = tid >> 5;
    int n8 = r & 15; r >>= 4;
    int ks = r & 7;  r >>= 3;
    int m = r;
    const float* W;
    switch (m) { case 0: W = W0; break; case 1: W = W1; break;
                 case 2: W = W2; break; case 3: W = W3; break;
                 case 4: W = W4; break; default: W = W5; }
    int g = lane >> 2, t = lane & 3;
    int k0 = ks * 16, n0 = n8 * 8;
    float w00 = W[(k0 + 2 * t)     * 128 + n0 + g];
    float w01 = W[(k0 + 2 * t + 1) * 128 + n0 + g];
    float w10 = W[(k0 + 2 * t + 8) * 128 + n0 + g];
    float w11 = W[(k0 + 2 * t + 9) * 128 + n0 + g];
    float h00 = __bfloat162float(__float2bfloat16(w00));
    float h01 = __bfloat162float(__float2bfloat16(w01));
    float h10 = __bfloat162float(__float2bfloat16(w10));
    float h11 = __bfloat162float(__float2bfloat16(w11));
    int li = m >> 1, mat = m & 1;
    unsigned int* oh = g_wf[li][mat * 2 + 0];
    unsigned int* ol = g_wf[li][mat * 2 + 1];
    int idx = ((ks * 16 + n8) * 32 + lane) * 2;
    oh[idx]     = pack2bf(w00, w01);
    oh[idx + 1] = pack2bf(w10, w11);
    ol[idx]     = pack2bf(w00 - h00, w01 - h01);
    ol[idx + 1] = pack2bf(w10 - h10, w11 - h11);
}

// ------------------------------ tensor GEMMs -------------------------------

#define MMA_BF16(D, A0, A1, A2, A3, B0, B1)                                   \
    asm volatile("mma.sync.aligned.m16n8k16.row.col.f32.bf16.bf16.f32 "       \
                 "{%0,%1,%2,%3}, {%4,%5,%6,%7}, {%8,%9}, {%0,%1,%2,%3};"      \
                 : "+f"(D[0]), "+f"(D[1]), "+f"(D[2]), "+f"(D[3])             \
                 : "r"(A0), "r"(A1), "r"(A2), "r"(A3), "r"(B0), "r"(B1))

__global__ void __launch_bounds__(256) k_gemm_t(int li) {
    int lane = threadIdx.x & 31, warp = threadIdx.x >> 5;
    int g = lane >> 2, t = lane & 3;
    int wr = warp >> 1, wc = warp & 1;
    int r0 = blockIdx.x * 64 + wr * 16;

    const unsigned int* XH  = (const unsigned int*)g_xh;
    const unsigned int* XLO = (const unsigned int*)g_xlo;
    const unsigned int* lh = g_wf[li][0];
    const unsigned int* ll = g_wf[li][1];
    const unsigned int* rh = g_wf[li][2];
    const unsigned int* rl = g_wf[li][3];

    float dl[8][4], dr[8][4];
    #pragma unroll
    for (int i = 0; i < 8; i++)
        #pragma unroll
        for (int j = 0; j < 4; j++) { dl[i][j] = 0.0f; dr[i][j] = 0.0f; }

    int rowA = (r0 + g) * 64;
    int rowB = (r0 + g + 8) * 64;

    #pragma unroll
    for (int ks = 0; ks < 8; ks++) {
        int kb = ks * 8 + t;
        unsigned int ah0 = __ldg(XH + rowA + kb),     ah1 = __ldg(XH + rowB + kb);
        unsigned int ah2 = __ldg(XH + rowA + kb + 4), ah3 = __ldg(XH + rowB + kb + 4);
        unsigned int al0 = __ldg(XLO + rowA + kb),     al1 = __ldg(XLO + rowB + kb);
        unsigned int al2 = __ldg(XLO + rowA + kb + 4), al3 = __ldg(XLO + rowB + kb + 4);
        #pragma unroll
        for (int n8 = 0; n8 < 8; n8++) {
            int nn = wc * 8 + n8;
            int bidx = ((ks * 16 + nn) * 32 + lane) * 2;
            uint2 bh = __ldg((const uint2*)(lh + bidx));
            uint2 bl = __ldg((const uint2*)(ll + bidx));
            MMA_BF16(dl[n8], ah0, ah1, ah2, ah3, bh.x, bh.y);
            MMA_BF16(dl[n8], ah0, ah1, ah2, ah3, bl.x, bl.y);
            MMA_BF16(dl[n8], al0, al1, al2, al3, bh.x, bh.y);
            uint2 ch = __ldg((const uint2*)(rh + bidx));
            uint2 cl = __ldg((const uint2*)(rl + bidx));
            MMA_BF16(dr[n8], ah0, ah1, ah2, ah3, ch.x, ch.y);
            MMA_BF16(dr[n8], ah0, ah1, ah2, ah3, cl.x, cl.y);
            MMA_BF16(dr[n8], al0, al1, al2, al3, ch.x, ch.y);
        }
    }

    #pragma unroll
    for (int n8 = 0; n8 < 8; n8++) {
        int c = (wc * 8 + n8) * 8 + 2 * t;
        *(float2*)&g_xl[(r0 + g)     * 128 + c] = make_float2(dl[n8][0], dl[n8][1]);
        *(float2*)&g_xl[(r0 + g + 8) * 128 + c] = make_float2(dl[n8][2], dl[n8][3]);
        *(float2*)&g_xr[(r0 + g)     * 128 + c] = make_float2(dr[n8][0], dr[n8][1]);
        *(float2*)&g_xr[(r0 + g + 8) * 128 + c] = make_float2(dr[n8][2], dr[n8][3]);
    }
}

// --------------------------- edge aggregation ------------------------------
// R8-proven: 1 warp/node; 2 edges per iteration (independent shfl chains,
// one branchless rescale per pair); prefetched gather; fused epilogue.

template<int SEGW, int IS_FINAL>
__global__ void __launch_bounds__(256)
k_agg(const float* __restrict__ att, const float* __restrict__ bias,
      const float* __restrict__ lng, const float* __restrict__ lnb,
      int n, float* __restrict__ dout) {
    int v = (blockIdx.x * blockDim.x + threadIdx.x) >> 5;
    int lane = threadIdx.x & 31;
    if (v >= n) return;
    int base = v * 128 + lane * 4;

    float4 xrv = *(const float4*)(g_xr + base);
    float4 av  = __ldg((const float4*)(att + lane * 4));

    float m = -1e30f, z = 0.0f;
    float a0 = 0.f, a1 = 0.f, a2 = 0.f, a3 = 0.f;

    const float4* __restrict__ XL = (const float4*)g_xl;
    const int* __restrict__ CSR = g_csr;
    int s0 = g_off[v], s1 = g_off[v + 1];

    // preload first pair
    int p = s0;
    int cA = CSR[p];
    int cB = (p + 1 < s1) ? CSR[p + 1] : cA;
    float4 xA = __ldg(XL + cA * 32 + lane);
    float4 xB = __ldg(XL + cB * 32 + lane);

    while (p < s1) {
        bool hasB = (p + 1 < s1);
        float4 a = xA, b = xB;
        int np = p + 2;
        if (np < s1) {                      // prefetch next pair
            int nA = CSR[np];
            int nB = (np + 1 < s1) ? CSR[np + 1] : nA;
            xA = __ldg(XL + nA * 32 + lane);
            xB = __ldg(XL + nB * 32 + lane);
        }

        float la = lrelu(a.x + xrv.x) * av.x + lrelu(a.y + xrv.y) * av.y
                 + lrelu(a.z + xrv.z) * av.z + lrelu(a.w + xrv.w) * av.w;
        float lb = lrelu(b.x + xrv.x) * av.x + lrelu(b.y + xrv.y) * av.y
                 + lrelu(b.z + xrv.z) * av.z + lrelu(b.w + xrv.w) * av.w;
        #pragma unroll
        for (int o = SEGW >> 1; o > 0; o >>= 1) {
            la += __shfl_xor_sync(0xffffffffu, la, o, SEGW);
            lb += __shfl_xor_sync(0xffffffffu, lb, o, SEGW);
        }
        if (!hasB) lb = -1e30f;

        float mn = fmaxf(m, fmaxf(la, lb));
        float sc = __expf(m - mn);          // == 1.0 when m unchanged
        float pa = __expf(la - mn);
        float pb = hasB ? __expf(lb - mn) : 0.0f;
        z  = z  * sc + pa + pb;
        a0 = a0 * sc + pa * a.x + pb * b.x;
        a1 = a1 * sc + pa * a.y + pb * b.y;
        a2 = a2 * sc + pa * a.z + pb * b.z;
        a3 = a3 * sc + pa * a.w + pb * b.w;
        m = mn;
        p = np;
    }

    float inv = 1.0f / z;
    float4 bv = __ldg((const float4*)(bias + lane * 4));
    float v0 = a0 * inv + bv.x;
    float v1 = a1 * inv + bv.y;
    float v2 = a2 * inv + bv.z;
    float v3 = a3 * inv + bv.w;
    {   // residual (always present for layers 1-3)
        float4 rv = *(const float4*)(g_x + base);
        v0 += rv.x; v1 += rv.y; v2 += rv.z; v3 += rv.w;
    }

    float sum = v0 + v1 + v2 + v3;
    #pragma unroll
    for (int o = 16; o > 0; o >>= 1) sum += __shfl_xor_sync(0xffffffffu, sum, o);
    float mean = sum * (1.0f / 128.0f);
    float d0 = v0 - mean, d1 = v1 - mean, d2 = v2 - mean, d3 = v3 - mean;
    float sq = d0 * d0 + d1 * d1 + d2 * d2 + d3 * d3;
    #pragma unroll
    for (int o = 16; o > 0; o >>= 1) sq += __shfl_xor_sync(0xffffffffu, sq, o);
    float rstd = rsqrtf(sq * (1.0f / 128.0f) + 1e-5f);

    float4 gv = __ldg((const float4*)(lng + lane * 4));
    float4 lb4 = __ldg((const float4*)(lnb + lane * 4));
    float4 o4;
    o4.x = fmaxf(d0 * rstd * gv.x + lb4.x, 0.0f);
    o4.y = fmaxf(d1 * rstd * gv.y + lb4.y, 0.0f);
    o4.z = fmaxf(d2 * rstd * gv.z + lb4.z, 0.0f);
    o4.w = fmaxf(d3 * rstd * gv.w + lb4.w, 0.0f);

    if (IS_FINAL) {
        *(float4*)(dout + base) = o4;
    } else {
        *(float4*)(g_x + base) = o4;
        float h0 = __bfloat162float(__float2bfloat16(o4.x));
        float h1 = __bfloat162float(__float2bfloat16(o4.y));
        float h2 = __bfloat162float(__float2bfloat16(o4.z));
        float h3 = __bfloat162float(__float2bfloat16(o4.w));
        unsigned int* XH  = (unsigned int*)g_xh;
        unsigned int* XLO = (unsigned int*)g_xlo;
        *(uint2*)&XH[v * 64 + lane * 2] =
            make_uint2(pack2bf(o4.x, o4.y), pack2bf(o4.z, o4.w));
        *(uint2*)&XLO[v * 64 + lane * 2] =
            make_uint2(pack2bf(o4.x - h0, o4.y - h1), pack2bf(o4.z - h2, o4.w - h3));
    }
}

// ------------------------------ launch -------------------------------------

extern "C" void kernel_launch(void* const* d_in, const int* in_sizes, int n_in,
                              void* d_out, int out_size) {
    const int*   node_types = (const int*)d_in[0];
    const int*   edge_index = (const int*)d_in[1];
    const float* emb        = (const float*)d_in[2];
    const float* Wl[4], *Wr[4], *att[4], *bias[4];
    for (int li = 0; li < 4; li++) {
        Wl[li]   = (const float*)d_in[3 + li * 4 + 0];
        Wr[li]   = (const float*)d_in[3 + li * 4 + 1];
        att[li]  = (const float*)d_in[3 + li * 4 + 2];
        bias[li] = (const float*)d_in[3 + li * 4 + 3];
    }
    const float* lng = (const float*)d_in[19];
    const float* lnb = (const float*)d_in[20];
    float* out = (float*)d_out;

    int n = in_sizes[0];
    int e = in_sizes[1] / 2;
    const int* esrc = edge_index;
    const int* edst = edge_index + e;

    // CSR by destination (self loops folded into the scan's +1)
    void* cntp = nullptr;
    cudaGetSymbolAddress(&cntp, g_cnt);
    cudaMemsetAsync(cntp, 0, n * sizeof(int));
    k_hist<<<(e + 255) / 256, 256>>>(edst, e);
    int nb = (n + 1023) / 1024;
    k_scan_blocks<<<nb, 1024>>>(n);
    k_scan_finish<<<(n + 255) / 256, 256>>>(n);
    k_scatter<<<(e + n + 255) / 256, 256>>>(esrc, edst, e, n);

    int ab = (n + 7) / 8;
    int tb = (n + 63) / 64;

    // layer 0 (exact 3-type closed form)
    k_prep0<<<1, 128>>>(emb, Wl[0], Wr[0], att[0]);
    k_agg0<<<ab, 256>>>(node_types, bias[0], lng + 0 * 128, lnb + 0 * 128, n);

    k_prepW<<<96, 256>>>(Wl[1], Wr[1], Wl[2], Wr[2], Wl[3], Wr[3]);

    // layer 1
    k_gemm_t<<<tb, 256>>>(0);
    k_agg<8, 0><<<ab, 256>>>(att[1], bias[1], lng + 1 * 128, lnb + 1 * 128,
                             n, out);
    // layer 2
    k_gemm_t<<<tb, 256>>>(1);
    k_agg<8, 0><<<ab, 256>>>(att[2], bias[2], lng + 2 * 128, lnb + 2 * 128,
                             n, out);
    // layer 3
    k_gemm_t<<<tb, 256>>>(2);
    k_agg<32, 1><<<ab, 256>>>(att[3], bias[3], lng + 3 * 128, lnb + 3 * 128,
                              n, out);
}